// round 16
// baseline (speedup 1.0000x reference)
#include <cuda_runtime.h>
#include <cuda_fp16.h>
#include <cstdint>
#include <math.h>

// Problem constants
#define BB 8
#define LL 8192
#define CC 512
#define HH 8
#define WS 32
#define SHIFT 16
#define MLPD 2048
#define NW (LL / WS)
#define NTOK (BB * LL)
#define HD (CC / HH)

// ---------------- scratch (device globals; allocation-free) ----------------
__device__ __half g_h   [(size_t)NTOK * CC];
__device__ __half g_qkv [(size_t)NTOK * 3 * CC];
__device__ __half g_att [(size_t)NTOK * CC];
__device__ float  g_y   [(size_t)NTOK * CC];
__device__ __half g_h2  [(size_t)NTOK * CC];
__device__ __half g_mid [(size_t)NTOK * MLPD];
__device__ __half g_wq  [3 * CC * CC];
__device__ __half g_wo  [CC * CC];
__device__ __half g_w1  [MLPD * CC];
__device__ __half g_w2  [CC * MLPD];

__device__ __forceinline__ uint32_t f22u(float a, float b) {
    __half2 t = __floats2half2_rn(a, b);
    return *reinterpret_cast<uint32_t*>(&t);
}

__device__ __forceinline__ void mma16816(float* d,
    uint32_t a0, uint32_t a1, uint32_t a2, uint32_t a3,
    uint32_t b0, uint32_t b1) {
    asm volatile(
        "mma.sync.aligned.m16n8k16.row.col.f32.f16.f16.f32 "
        "{%0,%1,%2,%3}, {%4,%5,%6,%7}, {%8,%9}, {%0,%1,%2,%3};"
        : "+f"(d[0]), "+f"(d[1]), "+f"(d[2]), "+f"(d[3])
        : "r"(a0), "r"(a1), "r"(a2), "r"(a3), "r"(b0), "r"(b1));
}

// ---------------- fused weight conversion (all 4 weights, one launch) -------
__global__ __launch_bounds__(256) void f2h_all_kernel(
    const float* __restrict__ w_qkv, const float* __restrict__ w_out,
    const float* __restrict__ w_fc1, const float* __restrict__ w_fc2,
    __half* __restrict__ wq, __half* __restrict__ wo,
    __half* __restrict__ w1, __half* __restrict__ w2)
{
    int i = blockIdx.x * blockDim.x + threadIdx.x;
    const float* src; __half* dst; int off;
    if (i < 196608)      { src = w_qkv; dst = wq; off = i; }
    else if (i < 262144) { src = w_out; dst = wo; off = i - 196608; }
    else if (i < 524288) { src = w_fc1; dst = w1; off = i - 262144; }
    else                 { src = w_fc2; dst = w2; off = i - 524288; }
    float4 v = reinterpret_cast<const float4*>(src)[off];
    reinterpret_cast<__half2*>(dst)[2 * off]     = __floats2half2_rn(v.x, v.y);
    reinterpret_cast<__half2*>(dst)[2 * off + 1] = __floats2half2_rn(v.z, v.w);
}

// ---------------- LayerNorm (fp32 in, half out; optional roll) --------------
__global__ __launch_bounds__(128) void ln_kernel(
    const float* __restrict__ in, const float* __restrict__ g,
    const float* __restrict__ be, __half* __restrict__ out, int rolled)
{
    int row = blockIdx.x;
    int b   = row >> 13;
    int l   = row & (LL - 1);
    int lsrc = rolled ? ((l + SHIFT) & (LL - 1)) : l;
    const float* src = in + ((size_t)((b << 13) | lsrc)) * CC;

    int tid = threadIdx.x;
    float4 v = reinterpret_cast<const float4*>(src)[tid];
    float s1 = v.x + v.y + v.z + v.w;
    float s2 = v.x*v.x + v.y*v.y + v.z*v.z + v.w*v.w;
    #pragma unroll
    for (int off = 16; off > 0; off >>= 1) {
        s1 += __shfl_down_sync(0xffffffffu, s1, off);
        s2 += __shfl_down_sync(0xffffffffu, s2, off);
    }
    __shared__ float sh1[4], sh2[4];
    int wid = tid >> 5, lane = tid & 31;
    if (lane == 0) { sh1[wid] = s1; sh2[wid] = s2; }
    __syncthreads();
    float t1 = sh1[0] + sh1[1] + sh1[2] + sh1[3];
    float t2 = sh2[0] + sh2[1] + sh2[2] + sh2[3];
    float mean = t1 * (1.0f / CC);
    float var  = t2 * (1.0f / CC) - mean * mean;
    float inv  = rsqrtf(var + 1e-5f);

    float4 gg = reinterpret_cast<const float4*>(g)[tid];
    float4 bb = reinterpret_cast<const float4*>(be)[tid];
    __half2* dst = reinterpret_cast<__half2*>(out + (size_t)row * CC);
    dst[2 * tid]     = __floats2half2_rn((v.x - mean) * inv * gg.x + bb.x,
                                         (v.y - mean) * inv * gg.y + bb.y);
    dst[2 * tid + 1] = __floats2half2_rn((v.z - mean) * inv * gg.z + bb.z,
                                         (v.w - mean) * inv * gg.w + bb.w);
}

// ---------------- windowed double-softmax attention (tensor-core) -----------
// One warp per (window, head). Block = 8 warps = one window. grid = B*nW.
#define AT_VTROW 40                  // halves per V^T row (32 + 8 pad)
#define AT_SLICEF 1376               // floats per warp slice: VT 1280 + rel 64 + pad 32
#define ATT_SMEM (8 * AT_SLICEF * 4) // 44032 B

__global__ __launch_bounds__(256, 2) void attn_kernel(
    const __half* __restrict__ qkv, const float* __restrict__ rel_table,
    __half* __restrict__ out)
{
    extern __shared__ float smf[];
    const int w    = blockIdx.x;
    const int h    = threadIdx.x >> 5;    // warp = head
    const int lane = threadIdx.x & 31;
    const int r = lane >> 2;              // 0..7
    const int c = lane & 3;               // 0..3

    __half* vt  = reinterpret_cast<__half*>(smf + h * AT_SLICEF);  // [64][40]
    float*  rel = smf + h * AT_SLICEF + 1280;

    const __half* base = qkv + (size_t)w * WS * (3 * CC) + h * HD;

    // ---- stage V^T into smem (lane = source row y); 8 uint4 = full 64 dims ----
    {
        const uint4* vrow = reinterpret_cast<const uint4*>(
            base + (size_t)lane * 3 * CC + 2 * CC);
        #pragma unroll
        for (int j = 0; j < 8; ++j) {
            uint4 u = vrow[j];
            __half hs[8];
            *reinterpret_cast<uint4*>(hs) = u;
            #pragma unroll
            for (int e = 0; e < 8; ++e)
                vt[(j * 8 + e) * AT_VTROW + lane] = hs[e];
        }
    }
    rel[lane] = rel_table[lane * HH + h];
    if (lane < 31) rel[lane + 32] = rel_table[(lane + 32) * HH + h];
    __syncwarp();

    // ---- S = Q K^T : fragments straight from gmem ----
    float cs[2][4][4];
    #pragma unroll
    for (int mt = 0; mt < 2; ++mt)
        #pragma unroll
        for (int nt = 0; nt < 4; ++nt)
            #pragma unroll
            for (int e = 0; e < 4; ++e) cs[mt][nt][e] = 0.f;

    #pragma unroll
    for (int kt = 0; kt < 4; ++kt) {
        uint32_t bf[4][2];
        #pragma unroll
        for (int nt = 0; nt < 4; ++nt) {
            const __half* kr = base + CC + (size_t)(nt * 8 + r) * 3 * CC + kt * 16 + 2 * c;
            bf[nt][0] = *reinterpret_cast<const uint32_t*>(kr);
            bf[nt][1] = *reinterpret_cast<const uint32_t*>(kr + 8);
        }
        #pragma unroll
        for (int mt = 0; mt < 2; ++mt) {
            const __half* q0 = base + (size_t)(mt * 16 + r) * 3 * CC + kt * 16 + 2 * c;
            uint32_t a0 = *reinterpret_cast<const uint32_t*>(q0);
            uint32_t a1 = *reinterpret_cast<const uint32_t*>(q0 + 8 * 3 * CC);
            uint32_t a2 = *reinterpret_cast<const uint32_t*>(q0 + 8);
            uint32_t a3 = *reinterpret_cast<const uint32_t*>(q0 + 8 * 3 * CC + 8);
            #pragma unroll
            for (int nt = 0; nt < 4; ++nt)
                mma16816(cs[mt][nt], a0, a1, a2, a3, bf[nt][0], bf[nt][1]);
        }
    }

    // ---- double softmax + rel bias + shift mask, in C-fragment registers ---
    const int wi = w & (NW - 1);
    const bool lastw = (wi == NW - 1);
    uint32_t ph[2][2][4];
    #pragma unroll
    for (int mt = 0; mt < 2; ++mt) {
        #pragma unroll
        for (int rh = 0; rh < 2; ++rh) {
            const int row = mt * 16 + r + rh * 8;
            float m = -1e30f;
            #pragma unroll
            for (int nt = 0; nt < 4; ++nt)
                #pragma unroll
                for (int e = 0; e < 2; ++e) {
                    cs[mt][nt][rh * 2 + e] *= 0.125f;
                    m = fmaxf(m, cs[mt][nt][rh * 2 + e]);
                }
            m = fmaxf(m, __shfl_xor_sync(0xffffffffu, m, 1));
            m = fmaxf(m, __shfl_xor_sync(0xffffffffu, m, 2));
            float sum = 0.f;
            #pragma unroll
            for (int nt = 0; nt < 4; ++nt)
                #pragma unroll
                for (int e = 0; e < 2; ++e) {
                    float v = __expf(cs[mt][nt][rh * 2 + e] - m);
                    cs[mt][nt][rh * 2 + e] = v; sum += v;
                }
            sum += __shfl_xor_sync(0xffffffffu, sum, 1);
            sum += __shfl_xor_sync(0xffffffffu, sum, 2);
            float isum = 1.0f / sum;

            float m2 = -1e30f;
            #pragma unroll
            for (int nt = 0; nt < 4; ++nt)
                #pragma unroll
                for (int e = 0; e < 2; ++e) {
                    int col = nt * 8 + 2 * c + e;
                    float v = cs[mt][nt][rh * 2 + e] * isum + rel[row - col + 31];
                    if (lastw && ((row >= 16) != (col >= 16))) v -= 100.0f;
                    cs[mt][nt][rh * 2 + e] = v;
                    m2 = fmaxf(m2, v);
                }
            m2 = fmaxf(m2, __shfl_xor_sync(0xffffffffu, m2, 1));
            m2 = fmaxf(m2, __shfl_xor_sync(0xffffffffu, m2, 2));
            float s2 = 0.f;
            #pragma unroll
            for (int nt = 0; nt < 4; ++nt)
                #pragma unroll
                for (int e = 0; e < 2; ++e) {
                    float v = __expf(cs[mt][nt][rh * 2 + e] - m2);
                    cs[mt][nt][rh * 2 + e] = v; s2 += v;
                }
            s2 += __shfl_xor_sync(0xffffffffu, s2, 1);
            s2 += __shfl_xor_sync(0xffffffffu, s2, 2);
            float is2 = 1.0f / s2;
            #pragma unroll
            for (int nt = 0; nt < 4; ++nt)
                #pragma unroll
                for (int e = 0; e < 2; ++e)
                    cs[mt][nt][rh * 2 + e] *= is2;
        }
        // C-frag -> A-frag conversion (fp16)
        #pragma unroll
        for (int kt = 0; kt < 2; ++kt) {
            ph[mt][kt][0] = f22u(cs[mt][2 * kt][0],     cs[mt][2 * kt][1]);
            ph[mt][kt][1] = f22u(cs[mt][2 * kt][2],     cs[mt][2 * kt][3]);
            ph[mt][kt][2] = f22u(cs[mt][2 * kt + 1][0], cs[mt][2 * kt + 1][1]);
            ph[mt][kt][3] = f22u(cs[mt][2 * kt + 1][2], cs[mt][2 * kt + 1][3]);
        }
    }

    // ---- O = P V : B-frags from V^T smem via ldmatrix ----
    const uint32_t svt = (uint32_t)__cvta_generic_to_shared(vt);
    const int rr = lane & 7, grp = lane >> 3;
    const int mrr = (grp & 1) * 8, kcc = (grp >> 1) * 8;
    uint32_t bV[4][2][4];
    #pragma unroll
    for (int np = 0; np < 4; ++np)
        #pragma unroll
        for (int kt = 0; kt < 2; ++kt) {
            uint32_t addr = svt + (uint32_t)(((np * 16 + mrr + rr) * AT_VTROW
                                              + kt * 16 + kcc) * 2);
            asm volatile("ldmatrix.sync.aligned.m8n8.x4.shared.b16 {%0,%1,%2,%3}, [%4];"
                : "=r"(bV[np][kt][0]), "=r"(bV[np][kt][1]),
                  "=r"(bV[np][kt][2]), "=r"(bV[np][kt][3])
                : "r"(addr));
        }

    float co[2][8][4];
    #pragma unroll
    for (int mt = 0; mt < 2; ++mt)
        #pragma unroll
        for (int nt = 0; nt < 8; ++nt)
            #pragma unroll
            for (int e = 0; e < 4; ++e) co[mt][nt][e] = 0.f;

    #pragma unroll
    for (int mt = 0; mt < 2; ++mt)
        #pragma unroll
        for (int kt = 0; kt < 2; ++kt)
            #pragma unroll
            for (int nt = 0; nt < 8; ++nt)
                mma16816(co[mt][nt],
                         ph[mt][kt][0], ph[mt][kt][1], ph[mt][kt][2], ph[mt][kt][3],
                         bV[nt >> 1][kt][nt & 1], bV[nt >> 1][kt][2 + (nt & 1)]);

    // ---- store O ----
    #pragma unroll
    for (int mt = 0; mt < 2; ++mt)
        #pragma unroll
        for (int rh = 0; rh < 2; ++rh) {
            int row = mt * 16 + r + rh * 8;
            __half* orow = out + (size_t)(w * WS + row) * CC + h * HD + 2 * c;
            #pragma unroll
            for (int nt = 0; nt < 8; ++nt)
                *reinterpret_cast<__half2*>(orow + nt * 8) =
                    __floats2half2_rn(co[mt][nt][rh * 2], co[mt][nt][rh * 2 + 1]);
        }
}

// ---------------- fp16 tensor-core GEMM NT, 128x256 tile --------------------
// Block tile 128(M) x 256(N), 8 warps (2x4), warp tile 64x64, K-stage 32,
// 4-stage cp.async ring, one __syncthreads per stage.
#define EPI_NONE 0
#define EPI_ATTN 1
#define EPI_GELU 2
#define EPI_RES  3

#define KCH 32
#define SROW 40
#define NSTG 4
#define A_H (128 * SROW)                 // halves per A tile (5120)
#define B_H (256 * SROW)                 // halves per B tile (10240)
#define STAGE_H (A_H + B_H)              // 15360 halves / stage
#define HG_SMEM (NSTG * STAGE_H * 2)     // 122880 bytes

template <int EPI>
__global__ __launch_bounds__(256) void hgemm(
    const __half* __restrict__ A, const __half* __restrict__ W,
    const float* __restrict__ bias, void* __restrict__ outv,
    const float* __restrict__ extra, int M, int N, int K)
{
    extern __shared__ __half sm[];

    const int tid  = threadIdx.x;
    const int lane = tid & 31;
    const int warp = tid >> 5;
    const int wm = warp >> 2, wn = warp & 3;
    const int bm = blockIdx.y * 128, bn = blockIdx.x * 256;

    // A loader: thread t -> row t>>1, 16-half chunk t&1 (2 x 16B cp.async)
    const int lrA = tid >> 1;
    const int lcA = (tid & 1) * 16;
    const __half* gA = A + (size_t)(bm + lrA) * K + lcA;
    // B loader: thread t -> row t (4 x 16B cp.async)
    const __half* gB = W + (size_t)(bn + tid) * K;

    const uint32_t sbase = (uint32_t)__cvta_generic_to_shared(sm);
    const uint32_t dstA  = (uint32_t)(lrA * SROW + lcA) * 2;
    const uint32_t dstB  = (uint32_t)(tid * SROW) * 2;

    const int rr  = lane & 7, grp = lane >> 3;
    const int mr = (grp & 1) * 8;
    const int kc = (grp >> 1) * 8;
    uint32_t aoff[4], boff[4];
    #pragma unroll
    for (int mt = 0; mt < 4; ++mt)
        aoff[mt] = (uint32_t)(((wm * 64 + mt * 16 + mr + rr) * SROW + kc) * 2);
    #pragma unroll
    for (int np = 0; np < 4; ++np)
        boff[np] = (uint32_t)(((wn * 64 + np * 16 + mr + rr) * SROW + kc) * 2);

    float c[4][8][4];
    #pragma unroll
    for (int i = 0; i < 4; ++i)
        #pragma unroll
        for (int j = 0; j < 8; ++j)
            #pragma unroll
            for (int r2 = 0; r2 < 4; ++r2) c[i][j][r2] = 0.f;

    const int S = K / KCH;

    auto issue = [&](int t) {
        uint32_t base = sbase + (uint32_t)(t & (NSTG - 1)) * STAGE_H * 2;
        uint32_t da = base + dstA;
        uint32_t db = base + A_H * 2 + dstB;
        const __half* ga = gA + (size_t)t * KCH;
        const __half* gb = gB + (size_t)t * KCH;
        asm volatile("cp.async.cg.shared.global [%0], [%1], 16;" :: "r"(da),      "l"(ga));
        asm volatile("cp.async.cg.shared.global [%0], [%1], 16;" :: "r"(da + 16), "l"(ga + 8));
        #pragma unroll
        for (int j = 0; j < 4; ++j)
            asm volatile("cp.async.cg.shared.global [%0], [%1], 16;"
                         :: "r"(db + j * 16), "l"(gb + j * 8));
    };

    issue(0); asm volatile("cp.async.commit_group;");
    issue(1); asm volatile("cp.async.commit_group;");
    issue(2); asm volatile("cp.async.commit_group;");

    for (int s = 0; s < S; ++s) {
        asm volatile("cp.async.wait_group 2;");
        __syncthreads();
        int t = s + 3;
        if (t < S) issue(t);
        asm volatile("cp.async.commit_group;");

        const uint32_t base = sbase + (uint32_t)(s & (NSTG - 1)) * STAGE_H * 2;
        const uint32_t ab = base;
        const uint32_t bb = base + A_H * 2;
        #pragma unroll
        for (int kk = 0; kk < 2; ++kk) {
            uint32_t a[4][4], b2[4][4];
            #pragma unroll
            for (int mt = 0; mt < 4; ++mt) {
                asm volatile("ldmatrix.sync.aligned.m8n8.x4.shared.b16 {%0,%1,%2,%3}, [%4];"
                    : "=r"(a[mt][0]), "=r"(a[mt][1]), "=r"(a[mt][2]), "=r"(a[mt][3])
                    : "r"(ab + aoff[mt] + kk * 32));
            }
            #pragma unroll
            for (int np = 0; np < 4; ++np) {
                asm volatile("ldmatrix.sync.aligned.m8n8.x4.shared.b16 {%0,%1,%2,%3}, [%4];"
                    : "=r"(b2[np][0]), "=r"(b2[np][1]), "=r"(b2[np][2]), "=r"(b2[np][3])
                    : "r"(bb + boff[np] + kk * 32));
            }
            #pragma unroll
            for (int mt = 0; mt < 4; ++mt) {
                #pragma unroll
                for (int nt = 0; nt < 8; ++nt) {
                    mma16816(c[mt][nt],
                             a[mt][0], a[mt][1], a[mt][2], a[mt][3],
                             b2[nt >> 1][nt & 1], b2[nt >> 1][2 + (nt & 1)]);
                }
            }
        }
    }

    // ---------------- epilogue ----------------
    const int mrow = lane >> 2;
    const int ncol = (lane & 3) * 2;
    #pragma unroll
    for (int mt = 0; mt < 4; ++mt) {
        #pragma unroll
        for (int half = 0; half < 2; ++half) {
            int m = bm + wm * 64 + mt * 16 + mrow + half * 8;
            #pragma unroll
            for (int nt = 0; nt < 8; ++nt) {
                int n = bn + wn * 64 + nt * 8 + ncol;
                float v0 = c[mt][nt][half * 2 + 0];
                float v1 = c[mt][nt][half * 2 + 1];
                if (EPI == EPI_NONE) {
                    __half* out = (__half*)outv;
                    *reinterpret_cast<__half2*>(out + (size_t)m * N + n) =
                        __floats2half2_rn(v0, v1);
                } else if (EPI == EPI_ATTN) {
                    float* out = (float*)outv;
                    int b = m >> 13;
                    int l = ((m & (LL - 1)) + SHIFT) & (LL - 1);
                    size_t idx = ((size_t)((b << 13) | l)) * CC + n;
                    float2 xr = *reinterpret_cast<const float2*>(extra + idx);
                    float2 br = *reinterpret_cast<const float2*>(bias + n);
                    *reinterpret_cast<float2*>(out + idx) =
                        make_float2(xr.x + v0 + br.x, xr.y + v1 + br.y);
                } else if (EPI == EPI_GELU) {
                    __half* out = (__half*)outv;
                    float2 br = *reinterpret_cast<const float2*>(bias + n);
                    float a0 = v0 + br.x, a1 = v1 + br.y;
                    float g0 = 0.5f * a0 * (1.0f + erff(a0 * 0.70710678118654752f));
                    float g1 = 0.5f * a1 * (1.0f + erff(a1 * 0.70710678118654752f));
                    *reinterpret_cast<__half2*>(out + (size_t)m * N + n) =
                        __floats2half2_rn(g0, g1);
                } else { // EPI_RES
                    float* out = (float*)outv;
                    size_t idx = (size_t)m * N + n;
                    float2 yr = *reinterpret_cast<const float2*>(extra + idx);
                    float2 br = *reinterpret_cast<const float2*>(bias + n);
                    *reinterpret_cast<float2*>(out + idx) =
                        make_float2(yr.x + v0 + br.x, yr.y + v1 + br.y);
                }
            }
        }
    }
}

// ---------------- launch ----------------------------------------------------
extern "C" void kernel_launch(void* const* d_in, const int* in_sizes, int n_in,
                              void* d_out, int out_size)
{
    const float* x      = (const float*)d_in[0];
    const float* w_qkv  = (const float*)d_in[1];
    const float* w_out  = (const float*)d_in[2];
    const float* b_out  = (const float*)d_in[3];
    const float* rel_tb = (const float*)d_in[4];
    const float* g1     = (const float*)d_in[5];
    const float* be1    = (const float*)d_in[6];
    const float* g2     = (const float*)d_in[7];
    const float* be2    = (const float*)d_in[8];
    const float* w_fc1  = (const float*)d_in[9];
    const float* b_fc1  = (const float*)d_in[10];
    const float* w_fc2  = (const float*)d_in[11];
    const float* b_fc2  = (const float*)d_in[12];
    float* out = (float*)d_out;

    __half *h, *qkv, *att, *h2, *mid, *wq, *wo, *w1, *w2;
    float *y;
    cudaGetSymbolAddress((void**)&h,   g_h);
    cudaGetSymbolAddress((void**)&qkv, g_qkv);
    cudaGetSymbolAddress((void**)&att, g_att);
    cudaGetSymbolAddress((void**)&y,   g_y);
    cudaGetSymbolAddress((void**)&h2,  g_h2);
    cudaGetSymbolAddress((void**)&mid, g_mid);
    cudaGetSymbolAddress((void**)&wq,  g_wq);
    cudaGetSymbolAddress((void**)&wo,  g_wo);
    cudaGetSymbolAddress((void**)&w1,  g_w1);
    cudaGetSymbolAddress((void**)&w2,  g_w2);

    cudaFuncSetAttribute(hgemm<EPI_NONE>, cudaFuncAttributeMaxDynamicSharedMemorySize, HG_SMEM);
    cudaFuncSetAttribute(hgemm<EPI_ATTN>, cudaFuncAttributeMaxDynamicSharedMemorySize, HG_SMEM);
    cudaFuncSetAttribute(hgemm<EPI_GELU>, cudaFuncAttributeMaxDynamicSharedMemorySize, HG_SMEM);
    cudaFuncSetAttribute(hgemm<EPI_RES>,  cudaFuncAttributeMaxDynamicSharedMemorySize, HG_SMEM);
    cudaFuncSetAttribute(attn_kernel,     cudaFuncAttributeMaxDynamicSharedMemorySize, ATT_SMEM);

    // 0. fp16 weight copies (one fused launch)
    f2h_all_kernel<<<786432 / 256, 256>>>(w_qkv, w_out, w_fc1, w_fc2, wq, wo, w1, w2);

    // 1. h = half(roll(LN1(x), -SHIFT))
    ln_kernel<<<NTOK, 128>>>(x, g1, be1, h, 1);
    // 2. qkv = h @ wq^T
    hgemm<EPI_NONE><<<dim3(3 * CC / 256, NTOK / 128), 256, HG_SMEM>>>(
        h, wq, nullptr, qkv, nullptr, NTOK, 3 * CC, CC);
    // 3. windowed attention (tensor-core, one warp per head, one block per window)
    attn_kernel<<<BB * NW, 256, ATT_SMEM>>>(qkv, rel_tb, att);
    // 4. y = x + roll(att @ wo^T + b_out, +SHIFT)
    hgemm<EPI_ATTN><<<dim3(CC / 256, NTOK / 128), 256, HG_SMEM>>>(
        att, wo, b_out, y, x, NTOK, CC, CC);
    // 5. h2 = half(LN2(y))
    ln_kernel<<<NTOK, 128>>>(y, g2, be2, h2, 0);
    // 6. mid = half(gelu(h2 @ w1^T + b_fc1))
    hgemm<EPI_GELU><<<dim3(MLPD / 256, NTOK / 128), 256, HG_SMEM>>>(
        h2, w1, b_fc1, mid, nullptr, NTOK, MLPD, CC);
    // 7. out = y + mid @ w2^T + b_fc2
    hgemm<EPI_RES><<<dim3(CC / 256, NTOK / 128), 256, HG_SMEM>>>(
        mid, w2, b_fc2, out, y, NTOK, CC, MLPD);
}

// round 17
// speedup vs baseline: 1.2538x; 1.2538x over previous
#include <cuda_runtime.h>
#include <cuda_fp16.h>
#include <cstdint>
#include <math.h>

// Problem constants
#define BB 8
#define LL 8192
#define CC 512
#define HH 8
#define WS 32
#define SHIFT 16
#define MLPD 2048
#define NW (LL / WS)
#define NTOK (BB * LL)
#define HD (CC / HH)

// ---------------- scratch (device globals; allocation-free) ----------------
__device__ __half g_h   [(size_t)NTOK * CC];
__device__ __half g_qkv [(size_t)NTOK * 3 * CC];
__device__ __half g_att [(size_t)NTOK * CC];
__device__ float  g_y   [(size_t)NTOK * CC];
__device__ __half g_h2  [(size_t)NTOK * CC];
__device__ __half g_mid [(size_t)NTOK * MLPD];
__device__ __half g_wq  [3 * CC * CC];
__device__ __half g_wo  [CC * CC];
__device__ __half g_w1  [MLPD * CC];
__device__ __half g_w2  [CC * MLPD];

__device__ __forceinline__ uint32_t f22u(float a, float b) {
    __half2 t = __floats2half2_rn(a, b);
    return *reinterpret_cast<uint32_t*>(&t);
}

__device__ __forceinline__ void mma16816(float* d,
    uint32_t a0, uint32_t a1, uint32_t a2, uint32_t a3,
    uint32_t b0, uint32_t b1) {
    asm volatile(
        "mma.sync.aligned.m16n8k16.row.col.f32.f16.f16.f32 "
        "{%0,%1,%2,%3}, {%4,%5,%6,%7}, {%8,%9}, {%0,%1,%2,%3};"
        : "+f"(d[0]), "+f"(d[1]), "+f"(d[2]), "+f"(d[3])
        : "r"(a0), "r"(a1), "r"(a2), "r"(a3), "r"(b0), "r"(b1));
}

// ---------------- fused weight conversion (all 4 weights, one launch) -------
__global__ __launch_bounds__(256) void f2h_all_kernel(
    const float* __restrict__ w_qkv, const float* __restrict__ w_out,
    const float* __restrict__ w_fc1, const float* __restrict__ w_fc2,
    __half* __restrict__ wq, __half* __restrict__ wo,
    __half* __restrict__ w1, __half* __restrict__ w2)
{
    int i = blockIdx.x * blockDim.x + threadIdx.x;
    const float* src; __half* dst; int off;
    if (i < 196608)      { src = w_qkv; dst = wq; off = i; }
    else if (i < 262144) { src = w_out; dst = wo; off = i - 196608; }
    else if (i < 524288) { src = w_fc1; dst = w1; off = i - 262144; }
    else                 { src = w_fc2; dst = w2; off = i - 524288; }
    float4 v = reinterpret_cast<const float4*>(src)[off];
    reinterpret_cast<__half2*>(dst)[2 * off]     = __floats2half2_rn(v.x, v.y);
    reinterpret_cast<__half2*>(dst)[2 * off + 1] = __floats2half2_rn(v.z, v.w);
}

// ---------------- LayerNorm: warp-per-row (fp32 in, half out) ---------------
// block = 256 thr = 8 warps = 8 rows; grid = NTOK/8. No smem, no barriers.
__global__ __launch_bounds__(256) void ln_kernel(
    const float* __restrict__ in, const float* __restrict__ g,
    const float* __restrict__ be, __half* __restrict__ out, int rolled)
{
    int wid  = threadIdx.x >> 5;
    int lane = threadIdx.x & 31;
    int row  = blockIdx.x * 8 + wid;
    int b    = row >> 13;
    int l    = row & (LL - 1);
    int lsrc = rolled ? ((l + SHIFT) & (LL - 1)) : l;
    const float4* src = reinterpret_cast<const float4*>(
        in + ((size_t)((b << 13) | lsrc)) * CC);

    float4 v[4];
    #pragma unroll
    for (int i = 0; i < 4; ++i) v[i] = src[i * 32 + lane];

    float s1 = 0.f, s2 = 0.f;
    #pragma unroll
    for (int i = 0; i < 4; ++i) {
        s1 += v[i].x + v[i].y + v[i].z + v[i].w;
        s2 += v[i].x*v[i].x + v[i].y*v[i].y + v[i].z*v[i].z + v[i].w*v[i].w;
    }
    #pragma unroll
    for (int off = 16; off > 0; off >>= 1) {
        s1 += __shfl_xor_sync(0xffffffffu, s1, off);
        s2 += __shfl_xor_sync(0xffffffffu, s2, off);
    }
    float mean = s1 * (1.0f / CC);
    float var  = s2 * (1.0f / CC) - mean * mean;
    float inv  = rsqrtf(var + 1e-5f);

    const float4* gg4 = reinterpret_cast<const float4*>(g);
    const float4* bb4 = reinterpret_cast<const float4*>(be);
    uint2* dst = reinterpret_cast<uint2*>(out + (size_t)row * CC);
    #pragma unroll
    for (int i = 0; i < 4; ++i) {
        float4 gg = gg4[i * 32 + lane];
        float4 bb = bb4[i * 32 + lane];
        uint2 r;
        r.x = f22u((v[i].x - mean) * inv * gg.x + bb.x,
                   (v[i].y - mean) * inv * gg.y + bb.y);
        r.y = f22u((v[i].z - mean) * inv * gg.z + bb.z,
                   (v[i].w - mean) * inv * gg.w + bb.w);
        dst[i * 32 + lane] = r;
    }
}

// ---------------- windowed double-softmax attention (tensor-core) -----------
// One warp per (window, head). Block = 8 warps = one window. grid = B*nW.
#define AT_VTROW 40                  // halves per V^T row (32 + 8 pad)
#define AT_SLICEF 1376               // floats per warp slice: VT 1280 + rel 64 + pad 32
#define ATT_SMEM (8 * AT_SLICEF * 4) // 44032 B

__global__ __launch_bounds__(256, 2) void attn_kernel(
    const __half* __restrict__ qkv, const float* __restrict__ rel_table,
    __half* __restrict__ out)
{
    extern __shared__ float smf[];
    const int w    = blockIdx.x;
    const int h    = threadIdx.x >> 5;    // warp = head
    const int lane = threadIdx.x & 31;
    const int r = lane >> 2;              // 0..7
    const int c = lane & 3;               // 0..3

    __half* vt  = reinterpret_cast<__half*>(smf + h * AT_SLICEF);  // [64][40]
    float*  rel = smf + h * AT_SLICEF + 1280;

    const __half* base = qkv + (size_t)w * WS * (3 * CC) + h * HD;

    // ---- stage V^T into smem (lane = source row y); 8 uint4 = full 64 dims ----
    {
        const uint4* vrow = reinterpret_cast<const uint4*>(
            base + (size_t)lane * 3 * CC + 2 * CC);
        #pragma unroll
        for (int j = 0; j < 8; ++j) {
            uint4 u = vrow[j];
            __half hs[8];
            *reinterpret_cast<uint4*>(hs) = u;
            #pragma unroll
            for (int e = 0; e < 8; ++e)
                vt[(j * 8 + e) * AT_VTROW + lane] = hs[e];
        }
    }
    rel[lane] = rel_table[lane * HH + h];
    if (lane < 31) rel[lane + 32] = rel_table[(lane + 32) * HH + h];
    __syncwarp();

    // ---- S = Q K^T : fragments straight from gmem ----
    float cs[2][4][4];
    #pragma unroll
    for (int mt = 0; mt < 2; ++mt)
        #pragma unroll
        for (int nt = 0; nt < 4; ++nt)
            #pragma unroll
            for (int e = 0; e < 4; ++e) cs[mt][nt][e] = 0.f;

    #pragma unroll
    for (int kt = 0; kt < 4; ++kt) {
        uint32_t bf[4][2];
        #pragma unroll
        for (int nt = 0; nt < 4; ++nt) {
            const __half* kr = base + CC + (size_t)(nt * 8 + r) * 3 * CC + kt * 16 + 2 * c;
            bf[nt][0] = *reinterpret_cast<const uint32_t*>(kr);
            bf[nt][1] = *reinterpret_cast<const uint32_t*>(kr + 8);
        }
        #pragma unroll
        for (int mt = 0; mt < 2; ++mt) {
            const __half* q0 = base + (size_t)(mt * 16 + r) * 3 * CC + kt * 16 + 2 * c;
            uint32_t a0 = *reinterpret_cast<const uint32_t*>(q0);
            uint32_t a1 = *reinterpret_cast<const uint32_t*>(q0 + 8 * 3 * CC);
            uint32_t a2 = *reinterpret_cast<const uint32_t*>(q0 + 8);
            uint32_t a3 = *reinterpret_cast<const uint32_t*>(q0 + 8 * 3 * CC + 8);
            #pragma unroll
            for (int nt = 0; nt < 4; ++nt)
                mma16816(cs[mt][nt], a0, a1, a2, a3, bf[nt][0], bf[nt][1]);
        }
    }

    // ---- double softmax + rel bias + shift mask, in C-fragment registers ---
    const int wi = w & (NW - 1);
    const bool lastw = (wi == NW - 1);
    uint32_t ph[2][2][4];
    #pragma unroll
    for (int mt = 0; mt < 2; ++mt) {
        #pragma unroll
        for (int rh = 0; rh < 2; ++rh) {
            const int row = mt * 16 + r + rh * 8;
            float m = -1e30f;
            #pragma unroll
            for (int nt = 0; nt < 4; ++nt)
                #pragma unroll
                for (int e = 0; e < 2; ++e) {
                    cs[mt][nt][rh * 2 + e] *= 0.125f;
                    m = fmaxf(m, cs[mt][nt][rh * 2 + e]);
                }
            m = fmaxf(m, __shfl_xor_sync(0xffffffffu, m, 1));
            m = fmaxf(m, __shfl_xor_sync(0xffffffffu, m, 2));
            float sum = 0.f;
            #pragma unroll
            for (int nt = 0; nt < 4; ++nt)
                #pragma unroll
                for (int e = 0; e < 2; ++e) {
                    float v = __expf(cs[mt][nt][rh * 2 + e] - m);
                    cs[mt][nt][rh * 2 + e] = v; sum += v;
                }
            sum += __shfl_xor_sync(0xffffffffu, sum, 1);
            sum += __shfl_xor_sync(0xffffffffu, sum, 2);
            float isum = 1.0f / sum;

            float m2 = -1e30f;
            #pragma unroll
            for (int nt = 0; nt < 4; ++nt)
                #pragma unroll
                for (int e = 0; e < 2; ++e) {
                    int col = nt * 8 + 2 * c + e;
                    float v = cs[mt][nt][rh * 2 + e] * isum + rel[row - col + 31];
                    if (lastw && ((row >= 16) != (col >= 16))) v -= 100.0f;
                    cs[mt][nt][rh * 2 + e] = v;
                    m2 = fmaxf(m2, v);
                }
            m2 = fmaxf(m2, __shfl_xor_sync(0xffffffffu, m2, 1));
            m2 = fmaxf(m2, __shfl_xor_sync(0xffffffffu, m2, 2));
            float s2 = 0.f;
            #pragma unroll
            for (int nt = 0; nt < 4; ++nt)
                #pragma unroll
                for (int e = 0; e < 2; ++e) {
                    float v = __expf(cs[mt][nt][rh * 2 + e] - m2);
                    cs[mt][nt][rh * 2 + e] = v; s2 += v;
                }
            s2 += __shfl_xor_sync(0xffffffffu, s2, 1);
            s2 += __shfl_xor_sync(0xffffffffu, s2, 2);
            float is2 = 1.0f / s2;
            #pragma unroll
            for (int nt = 0; nt < 4; ++nt)
                #pragma unroll
                for (int e = 0; e < 2; ++e)
                    cs[mt][nt][rh * 2 + e] *= is2;
        }
        // C-frag -> A-frag conversion (fp16)
        #pragma unroll
        for (int kt = 0; kt < 2; ++kt) {
            ph[mt][kt][0] = f22u(cs[mt][2 * kt][0],     cs[mt][2 * kt][1]);
            ph[mt][kt][1] = f22u(cs[mt][2 * kt][2],     cs[mt][2 * kt][3]);
            ph[mt][kt][2] = f22u(cs[mt][2 * kt + 1][0], cs[mt][2 * kt + 1][1]);
            ph[mt][kt][3] = f22u(cs[mt][2 * kt + 1][2], cs[mt][2 * kt + 1][3]);
        }
    }

    // ---- O = P V : B-frags from V^T smem via ldmatrix ----
    const uint32_t svt = (uint32_t)__cvta_generic_to_shared(vt);
    const int rr = lane & 7, grp = lane >> 3;
    const int mrr = (grp & 1) * 8, kcc = (grp >> 1) * 8;
    uint32_t bV[4][2][4];
    #pragma unroll
    for (int np = 0; np < 4; ++np)
        #pragma unroll
        for (int kt = 0; kt < 2; ++kt) {
            uint32_t addr = svt + (uint32_t)(((np * 16 + mrr + rr) * AT_VTROW
                                              + kt * 16 + kcc) * 2);
            asm volatile("ldmatrix.sync.aligned.m8n8.x4.shared.b16 {%0,%1,%2,%3}, [%4];"
                : "=r"(bV[np][kt][0]), "=r"(bV[np][kt][1]),
                  "=r"(bV[np][kt][2]), "=r"(bV[np][kt][3])
                : "r"(addr));
        }

    float co[2][8][4];
    #pragma unroll
    for (int mt = 0; mt < 2; ++mt)
        #pragma unroll
        for (int nt = 0; nt < 8; ++nt)
            #pragma unroll
            for (int e = 0; e < 4; ++e) co[mt][nt][e] = 0.f;

    #pragma unroll
    for (int mt = 0; mt < 2; ++mt)
        #pragma unroll
        for (int kt = 0; kt < 2; ++kt)
            #pragma unroll
            for (int nt = 0; nt < 8; ++nt)
                mma16816(co[mt][nt],
                         ph[mt][kt][0], ph[mt][kt][1], ph[mt][kt][2], ph[mt][kt][3],
                         bV[nt >> 1][kt][nt & 1], bV[nt >> 1][kt][2 + (nt & 1)]);

    // ---- store O ----
    #pragma unroll
    for (int mt = 0; mt < 2; ++mt)
        #pragma unroll
        for (int rh = 0; rh < 2; ++rh) {
            int row = mt * 16 + r + rh * 8;
            __half* orow = out + (size_t)(w * WS + row) * CC + h * HD + 2 * c;
            #pragma unroll
            for (int nt = 0; nt < 8; ++nt)
                *reinterpret_cast<__half2*>(orow + nt * 8) =
                    __floats2half2_rn(co[mt][nt][rh * 2], co[mt][nt][rh * 2 + 1]);
        }
}

// ---------------- fp16 tensor-core GEMM NT (R15-proven 128x128) -------------
#define EPI_NONE 0
#define EPI_ATTN 1
#define EPI_GELU 2
#define EPI_RES  3

#define KCH 32
#define SROW 40
#define NSTG 4
#define STGH (128 * SROW)
#define STAGE_H (2 * STGH)
#define HG_SMEM (NSTG * STAGE_H * 2)

template <int EPI>
__global__ __launch_bounds__(256) void hgemm(
    const __half* __restrict__ A, const __half* __restrict__ W,
    const float* __restrict__ bias, void* __restrict__ outv,
    const float* __restrict__ extra, int M, int N, int K)
{
    extern __shared__ __half sm[];

    const int tid  = threadIdx.x;
    const int lane = tid & 31;
    const int warp = tid >> 5;
    const int wm = warp >> 2, wn = warp & 3;
    const int bm = blockIdx.y * 128, bn = blockIdx.x * 128;

    const int lr = tid >> 1;
    const int lc = (tid & 1) * 16;
    const __half* gA = A + (size_t)(bm + lr) * K + lc;
    const __half* gB = W + (size_t)(bn + lr) * K + lc;

    const uint32_t sbase = (uint32_t)__cvta_generic_to_shared(sm);
    const uint32_t dst0  = (uint32_t)(lr * SROW + lc) * 2;

    const int rr  = lane & 7, grp = lane >> 3;
    const int mr = (grp & 1) * 8;
    const int kc = (grp >> 1) * 8;
    uint32_t aoff[4], boff[2];
    #pragma unroll
    for (int mt = 0; mt < 4; ++mt)
        aoff[mt] = (uint32_t)(((wm * 64 + mt * 16 + mr + rr) * SROW + kc) * 2);
    #pragma unroll
    for (int np = 0; np < 2; ++np)
        boff[np] = (uint32_t)(((wn * 32 + np * 16 + mr + rr) * SROW + kc) * 2);

    float c[4][4][4];
    #pragma unroll
    for (int i = 0; i < 4; ++i)
        #pragma unroll
        for (int j = 0; j < 4; ++j)
            #pragma unroll
            for (int r = 0; r < 4; ++r) c[i][j][r] = 0.f;

    const int S = K / KCH;

    auto issue = [&](int t) {
        uint32_t base = sbase + (uint32_t)(t & (NSTG - 1)) * STAGE_H * 2;
        uint32_t da = base + dst0;
        uint32_t db = base + STGH * 2 + dst0;
        const __half* ga = gA + (size_t)t * KCH;
        const __half* gb = gB + (size_t)t * KCH;
        asm volatile("cp.async.cg.shared.global [%0], [%1], 16;" :: "r"(da),      "l"(ga));
        asm volatile("cp.async.cg.shared.global [%0], [%1], 16;" :: "r"(da + 16), "l"(ga + 8));
        asm volatile("cp.async.cg.shared.global [%0], [%1], 16;" :: "r"(db),      "l"(gb));
        asm volatile("cp.async.cg.shared.global [%0], [%1], 16;" :: "r"(db + 16), "l"(gb + 8));
    };

    issue(0); asm volatile("cp.async.commit_group;");
    issue(1); asm volatile("cp.async.commit_group;");
    issue(2); asm volatile("cp.async.commit_group;");

    for (int s = 0; s < S; ++s) {
        asm volatile("cp.async.wait_group 2;");
        __syncthreads();
        int t = s + 3;
        if (t < S) issue(t);
        asm volatile("cp.async.commit_group;");

        const uint32_t base = sbase + (uint32_t)(s & (NSTG - 1)) * STAGE_H * 2;
        const uint32_t ab = base;
        const uint32_t bb = base + STGH * 2;
        #pragma unroll
        for (int kk = 0; kk < 2; ++kk) {
            uint32_t a[4][4], b2[2][4];
            #pragma unroll
            for (int mt = 0; mt < 4; ++mt) {
                asm volatile("ldmatrix.sync.aligned.m8n8.x4.shared.b16 {%0,%1,%2,%3}, [%4];"
                    : "=r"(a[mt][0]), "=r"(a[mt][1]), "=r"(a[mt][2]), "=r"(a[mt][3])
                    : "r"(ab + aoff[mt] + kk * 32));
            }
            #pragma unroll
            for (int np = 0; np < 2; ++np) {
                asm volatile("ldmatrix.sync.aligned.m8n8.x4.shared.b16 {%0,%1,%2,%3}, [%4];"
                    : "=r"(b2[np][0]), "=r"(b2[np][1]), "=r"(b2[np][2]), "=r"(b2[np][3])
                    : "r"(bb + boff[np] + kk * 32));
            }
            #pragma unroll
            for (int mt = 0; mt < 4; ++mt) {
                #pragma unroll
                for (int nt = 0; nt < 4; ++nt) {
                    mma16816(c[mt][nt],
                             a[mt][0], a[mt][1], a[mt][2], a[mt][3],
                             b2[nt >> 1][nt & 1], b2[nt >> 1][2 + (nt & 1)]);
                }
            }
        }
    }

    // ---------------- epilogue ----------------
    const int mrow = lane >> 2;
    const int ncol = (lane & 3) * 2;
    #pragma unroll
    for (int mt = 0; mt < 4; ++mt) {
        #pragma unroll
        for (int half = 0; half < 2; ++half) {
            int m = bm + wm * 64 + mt * 16 + mrow + half * 8;
            #pragma unroll
            for (int nt = 0; nt < 4; ++nt) {
                int n = bn + wn * 32 + nt * 8 + ncol;
                float v0 = c[mt][nt][half * 2 + 0];
                float v1 = c[mt][nt][half * 2 + 1];
                if (EPI == EPI_NONE) {
                    __half* out = (__half*)outv;
                    *reinterpret_cast<__half2*>(out + (size_t)m * N + n) =
                        __floats2half2_rn(v0, v1);
                } else if (EPI == EPI_ATTN) {
                    float* out = (float*)outv;
                    int b = m >> 13;
                    int l = ((m & (LL - 1)) + SHIFT) & (LL - 1);
                    size_t idx = ((size_t)((b << 13) | l)) * CC + n;
                    float2 xr = *reinterpret_cast<const float2*>(extra + idx);
                    float2 br = *reinterpret_cast<const float2*>(bias + n);
                    *reinterpret_cast<float2*>(out + idx) =
                        make_float2(xr.x + v0 + br.x, xr.y + v1 + br.y);
                } else if (EPI == EPI_GELU) {
                    __half* out = (__half*)outv;
                    float2 br = *reinterpret_cast<const float2*>(bias + n);
                    float a0 = v0 + br.x, a1 = v1 + br.y;
                    float g0 = 0.5f * a0 * (1.0f + erff(a0 * 0.70710678118654752f));
                    float g1 = 0.5f * a1 * (1.0f + erff(a1 * 0.70710678118654752f));
                    *reinterpret_cast<__half2*>(out + (size_t)m * N + n) =
                        __floats2half2_rn(g0, g1);
                } else { // EPI_RES
                    float* out = (float*)outv;
                    size_t idx = (size_t)m * N + n;
                    float2 yr = *reinterpret_cast<const float2*>(extra + idx);
                    float2 br = *reinterpret_cast<const float2*>(bias + n);
                    *reinterpret_cast<float2*>(out + idx) =
                        make_float2(yr.x + v0 + br.x, yr.y + v1 + br.y);
                }
            }
        }
    }
}

// ---------------- launch ----------------------------------------------------
extern "C" void kernel_launch(void* const* d_in, const int* in_sizes, int n_in,
                              void* d_out, int out_size)
{
    const float* x      = (const float*)d_in[0];
    const float* w_qkv  = (const float*)d_in[1];
    const float* w_out  = (const float*)d_in[2];
    const float* b_out  = (const float*)d_in[3];
    const float* rel_tb = (const float*)d_in[4];
    const float* g1     = (const float*)d_in[5];
    const float* be1    = (const float*)d_in[6];
    const float* g2     = (const float*)d_in[7];
    const float* be2    = (const float*)d_in[8];
    const float* w_fc1  = (const float*)d_in[9];
    const float* b_fc1  = (const float*)d_in[10];
    const float* w_fc2  = (const float*)d_in[11];
    const float* b_fc2  = (const float*)d_in[12];
    float* out = (float*)d_out;

    __half *h, *qkv, *att, *h2, *mid, *wq, *wo, *w1, *w2;
    float *y;
    cudaGetSymbolAddress((void**)&h,   g_h);
    cudaGetSymbolAddress((void**)&qkv, g_qkv);
    cudaGetSymbolAddress((void**)&att, g_att);
    cudaGetSymbolAddress((void**)&y,   g_y);
    cudaGetSymbolAddress((void**)&h2,  g_h2);
    cudaGetSymbolAddress((void**)&mid, g_mid);
    cudaGetSymbolAddress((void**)&wq,  g_wq);
    cudaGetSymbolAddress((void**)&wo,  g_wo);
    cudaGetSymbolAddress((void**)&w1,  g_w1);
    cudaGetSymbolAddress((void**)&w2,  g_w2);

    cudaFuncSetAttribute(hgemm<EPI_NONE>, cudaFuncAttributeMaxDynamicSharedMemorySize, HG_SMEM);
    cudaFuncSetAttribute(hgemm<EPI_ATTN>, cudaFuncAttributeMaxDynamicSharedMemorySize, HG_SMEM);
    cudaFuncSetAttribute(hgemm<EPI_GELU>, cudaFuncAttributeMaxDynamicSharedMemorySize, HG_SMEM);
    cudaFuncSetAttribute(hgemm<EPI_RES>,  cudaFuncAttributeMaxDynamicSharedMemorySize, HG_SMEM);
    cudaFuncSetAttribute(attn_kernel,     cudaFuncAttributeMaxDynamicSharedMemorySize, ATT_SMEM);

    // 0. fp16 weight copies (one fused launch)
    f2h_all_kernel<<<786432 / 256, 256>>>(w_qkv, w_out, w_fc1, w_fc2, wq, wo, w1, w2);

    // 1. h = half(roll(LN1(x), -SHIFT))   [warp-per-row]
    ln_kernel<<<NTOK / 8, 256>>>(x, g1, be1, h, 1);
    // 2. qkv = h @ wq^T
    hgemm<EPI_NONE><<<dim3(3 * CC / 128, NTOK / 128), 256, HG_SMEM>>>(
        h, wq, nullptr, qkv, nullptr, NTOK, 3 * CC, CC);
    // 3. windowed attention (tensor-core, one warp per head, one block per window)
    attn_kernel<<<BB * NW, 256, ATT_SMEM>>>(qkv, rel_tb, att);
    // 4. y = x + roll(att @ wo^T + b_out, +SHIFT)
    hgemm<EPI_ATTN><<<dim3(CC / 128, NTOK / 128), 256, HG_SMEM>>>(
        att, wo, b_out, y, x, NTOK, CC, CC);
    // 5. h2 = half(LN2(y))   [warp-per-row]
    ln_kernel<<<NTOK / 8, 256>>>(y, g2, be2, h2, 0);
    // 6. mid = half(gelu(h2 @ w1^T + b_fc1))
    hgemm<EPI_GELU><<<dim3(MLPD / 128, NTOK / 128), 256, HG_SMEM>>>(
        h2, w1, b_fc1, mid, nullptr, NTOK, MLPD, CC);
    // 7. out = y + mid @ w2^T + b_fc2
    hgemm<EPI_RES><<<dim3(CC / 128, NTOK / 128), 256, HG_SMEM>>>(
        mid, w2, b_fc2, out, y, NTOK, CC, MLPD);
}